// round 1
// baseline (speedup 1.0000x reference)
#include <cuda_runtime.h>

#define B_  4
#define N_  2048
#define D_  128
#define BM  128
#define BN  128
#define BK  16
#define NKC (D_/BK)

// Precomputed row squared-norms: sq[b*N_ + n]
__device__ float g_sq[B_ * N_];

__device__ __forceinline__ unsigned long long bcast2(float f) {
    unsigned long long r;
    asm("mov.b64 %0, {%1, %1};" : "=l"(r) : "f"(f));
    return r;
}

__device__ __forceinline__ void fma2(unsigned long long& c,
                                     unsigned long long a,
                                     unsigned long long b) {
    asm("fma.rn.f32x2 %0, %1, %2, %0;" : "+l"(c) : "l"(a), "l"(b));
}

__device__ __forceinline__ float2 unpk(unsigned long long v) {
    float2 r;
    asm("mov.b64 {%0, %1}, %2;" : "=f"(r.x), "=f"(r.y) : "l"(v));
    return r;
}

__global__ void sq_kernel(const float* __restrict__ x) {
    int r = blockIdx.x * blockDim.x + threadIdx.x;  // 0 .. B_*N_-1
    const float4* p = (const float4*)(x + (size_t)r * D_);
    float s = 0.f;
#pragma unroll
    for (int t = 0; t < D_ / 4; t++) {
        float4 v = p[t];
        s += v.x * v.x + v.y * v.y + v.z * v.z + v.w * v.w;
    }
    g_sq[r] = s;
}

__global__ __launch_bounds__(256) void edm_kernel(const float* __restrict__ x,
                                                  float* __restrict__ out) {
    __shared__ float As[2][BK][BM];
    __shared__ float Bs[2][BK][BN];

    const int b  = blockIdx.z;
    const int i0 = blockIdx.y * BM;
    const int j0 = blockIdx.x * BN;
    const float* xb = x + (size_t)b * N_ * D_;

    const int tid = threadIdx.x;
    const int tx  = tid & 15;        // 0..15  -> column group (8 cols)
    const int ty  = tid >> 4;        // 0..15  -> row group (8 rows)
    const int lm  = tid & 127;       // row within tile for loading
    const int kq  = tid >> 7;        // 0/1    -> which k-quad group

    float4 ra[2], rb[2];
    unsigned long long c[8][4];
#pragma unroll
    for (int i = 0; i < 8; i++)
#pragma unroll
        for (int j = 0; j < 4; j++) c[i][j] = 0ULL;

    auto gload = [&](int kc) {
#pragma unroll
        for (int u = 0; u < 2; u++) {
            int kg = kq + 2 * u;  // 0..3
            ra[u] = *(const float4*)(xb + (size_t)(i0 + lm) * D_ + kc * BK + kg * 4);
            rb[u] = *(const float4*)(xb + (size_t)(j0 + lm) * D_ + kc * BK + kg * 4);
        }
    };
    auto sstore = [&](int buf) {
#pragma unroll
        for (int u = 0; u < 2; u++) {
            int kg = kq + 2 * u;
            As[buf][kg * 4 + 0][lm] = ra[u].x;
            As[buf][kg * 4 + 1][lm] = ra[u].y;
            As[buf][kg * 4 + 2][lm] = ra[u].z;
            As[buf][kg * 4 + 3][lm] = ra[u].w;
            Bs[buf][kg * 4 + 0][lm] = rb[u].x;
            Bs[buf][kg * 4 + 1][lm] = rb[u].y;
            Bs[buf][kg * 4 + 2][lm] = rb[u].z;
            Bs[buf][kg * 4 + 3][lm] = rb[u].w;
        }
    };
    auto compute = [&](int buf) {
#pragma unroll
        for (int kk = 0; kk < BK; kk++) {
            float4 a0 = *(const float4*)&As[buf][kk][ty * 8];
            float4 a1 = *(const float4*)&As[buf][kk][ty * 8 + 4];
            ulonglong2 b0 = *(const ulonglong2*)&Bs[buf][kk][tx * 8];
            ulonglong2 b1 = *(const ulonglong2*)&Bs[buf][kk][tx * 8 + 4];
            unsigned long long A2[8];
            A2[0] = bcast2(a0.x); A2[1] = bcast2(a0.y);
            A2[2] = bcast2(a0.z); A2[3] = bcast2(a0.w);
            A2[4] = bcast2(a1.x); A2[5] = bcast2(a1.y);
            A2[6] = bcast2(a1.z); A2[7] = bcast2(a1.w);
            unsigned long long B2[4] = {b0.x, b0.y, b1.x, b1.y};
#pragma unroll
            for (int i = 0; i < 8; i++)
#pragma unroll
                for (int j = 0; j < 4; j++) fma2(c[i][j], A2[i], B2[j]);
        }
    };

    gload(0);
    sstore(0);
    __syncthreads();

#pragma unroll
    for (int kc = 0; kc < NKC; kc++) {
        if (kc + 1 < NKC) gload(kc + 1);
        compute(kc & 1);
        if (kc + 1 < NKC) {
            sstore((kc + 1) & 1);
            __syncthreads();
        }
    }

    // Epilogue: D = sqrt(max(sq_i + sq_j - 2*dot, 0) + eps)
    float sqi[8], sqj[8];
#pragma unroll
    for (int i = 0; i < 8; i++) sqi[i] = g_sq[b * N_ + i0 + ty * 8 + i];
#pragma unroll
    for (int j = 0; j < 8; j++) sqj[j] = g_sq[b * N_ + j0 + tx * 8 + j];

#pragma unroll
    for (int i = 0; i < 8; i++) {
        float vals[8];
#pragma unroll
        for (int j = 0; j < 4; j++) {
            float2 p = unpk(c[i][j]);
            float d0 = fmaxf(fmaf(-2.f, p.x, sqi[i] + sqj[2 * j]), 0.f) + 1e-7f;
            float d1 = fmaxf(fmaf(-2.f, p.y, sqi[i] + sqj[2 * j + 1]), 0.f) + 1e-7f;
            vals[2 * j]     = sqrtf(d0);
            vals[2 * j + 1] = sqrtf(d1);
        }
        float* orow = out + ((size_t)b * N_ + i0 + ty * 8 + i) * N_ + j0 + tx * 8;
        *(float4*)orow       = make_float4(vals[0], vals[1], vals[2], vals[3]);
        *(float4*)(orow + 4) = make_float4(vals[4], vals[5], vals[6], vals[7]);
    }
}

extern "C" void kernel_launch(void* const* d_in, const int* in_sizes, int n_in,
                              void* d_out, int out_size) {
    const float* x = (const float*)d_in[0];
    float* out = (float*)d_out;

    sq_kernel<<<(B_ * N_) / 256, 256>>>(x);

    dim3 grid(N_ / BN, N_ / BM, B_);
    edm_kernel<<<grid, 256>>>(x, out);
}

// round 3
// speedup vs baseline: 1.4374x; 1.4374x over previous
#include <cuda_runtime.h>
#include <cstdint>

#define B_  4
#define N_  2048
#define D_  128

// smem layout (bytes)
#define SM_SQI 0
#define SM_SQJ 512
#define SM_A   1024
#define SM_B   (1024 + 65536)
#define SM_TOTAL (1024 + 2 * 65536)

__device__ float g_sq[B_ * N_];

__global__ void sq_kernel(const float* __restrict__ x) {
    int r = blockIdx.x * blockDim.x + threadIdx.x;
    const float4* p = (const float4*)(x + (size_t)r * D_);
    float s = 0.f;
#pragma unroll
    for (int t = 0; t < D_ / 4; t++) {
        float4 v = p[t];
        s += v.x * v.x + v.y * v.y + v.z * v.z + v.w * v.w;
    }
    g_sq[r] = s;
}

__global__ __launch_bounds__(256) void edm_mma_kernel(const float* __restrict__ x,
                                                      float* __restrict__ out) {
    extern __shared__ char smem[];
    const int tid = threadIdx.x;
    const int wid = tid >> 5;
    const int lane = tid & 31;
    const int g  = lane >> 2;   // 0..7
    const int cc = lane & 3;    // 0..3

    const int b  = blockIdx.z;
    const int i0 = blockIdx.y * 128;
    const int j0 = blockIdx.x * 128;
    const float* xb = x + (size_t)b * N_ * D_;

    // ---- load phase: pair-interleaved, XOR-swizzled smem tiles ----
    // slot s = 4*kbi + c holds (x[kb+c], x[kb+c+4]); phys = s ^ ((r&3)<<2)
    {
        const int bb = tid & 3;          // -> r low bits
        const int aa = (tid >> 2) & 3;   // -> kbi low bits
        const int rmid = (tid >> 4);     // 0..15
#pragma unroll
        for (int iter = 0; iter < 8; iter++) {
            int kbi = aa | ((iter & 3) << 2);           // 0..15
            int r   = bb | (rmid << 2) | ((iter >> 2) << 6);  // 0..127
            const float4* pA = (const float4*)(xb + (size_t)(i0 + r) * D_ + kbi * 8);
            const float4* pB = (const float4*)(xb + (size_t)(j0 + r) * D_ + kbi * 8);
            float4 v0 = pA[0], v1 = pA[1];
            float4 w0 = pB[0], w1 = pB[1];
            float va[8] = {v0.x, v0.y, v0.z, v0.w, v1.x, v1.y, v1.z, v1.w};
            float wa[8] = {w0.x, w0.y, w0.z, w0.w, w1.x, w1.y, w1.z, w1.w};
            char* rowA = smem + SM_A + r * 512;
            char* rowB = smem + SM_B + r * 512;
            int x4 = (r & 3) << 2;
#pragma unroll
            for (int j = 0; j < 4; j++) {
                int c = (bb + j) & 3;
                int phys = (4 * kbi + c) ^ x4;
                *(float2*)(rowA + phys * 8) = make_float2(va[c], va[c + 4]);
                *(float2*)(rowB + phys * 8) = make_float2(wa[c], wa[c + 4]);
            }
        }
        if (tid < 128) ((float*)(smem + SM_SQI))[tid] = g_sq[b * N_ + i0 + tid];
        else           ((float*)(smem + SM_SQJ))[tid - 128] = g_sq[b * N_ + j0 + tid - 128];
    }
    __syncthreads();

    // ---- mainloop: warp tile 64x32, m16n8k8 tf32 ----
    const int wm = (wid >> 2) * 64;   // 0 or 64
    const int wn = (wid & 3) * 32;    // 0,32,64,96

    float acc[4][4][4];
#pragma unroll
    for (int mt = 0; mt < 4; mt++)
#pragma unroll
        for (int nt = 0; nt < 4; nt++)
#pragma unroll
            for (int e = 0; e < 4; e++) acc[mt][nt][e] = 0.f;

    const int gx4 = (g & 3) << 2;
#pragma unroll
    for (int kst = 0; kst < 16; kst++) {
        const int phys = (4 * kst + cc) ^ gx4;
        uint32_t a[4][4], bfr[4][2];
#pragma unroll
        for (int mt = 0; mt < 4; mt++) {
            int r0 = wm + 16 * mt + g;
            float2 a02 = *(float2*)(smem + SM_A + r0 * 512 + phys * 8);
            float2 a13 = *(float2*)(smem + SM_A + (r0 + 8) * 512 + phys * 8);
            a[mt][0] = __float_as_uint(a02.x);
            a[mt][1] = __float_as_uint(a13.x);
            a[mt][2] = __float_as_uint(a02.y);
            a[mt][3] = __float_as_uint(a13.y);
        }
#pragma unroll
        for (int nt = 0; nt < 4; nt++) {
            int n0 = wn + 8 * nt + g;
            float2 b01 = *(float2*)(smem + SM_B + n0 * 512 + phys * 8);
            bfr[nt][0] = __float_as_uint(b01.x);
            bfr[nt][1] = __float_as_uint(b01.y);
        }
#pragma unroll
        for (int mt = 0; mt < 4; mt++)
#pragma unroll
            for (int nt = 0; nt < 4; nt++) {
                asm volatile(
                    "mma.sync.aligned.m16n8k8.row.col.f32.tf32.tf32.f32 "
                    "{%0,%1,%2,%3}, {%4,%5,%6,%7}, {%8,%9}, {%0,%1,%2,%3};"
                    : "+f"(acc[mt][nt][0]), "+f"(acc[mt][nt][1]),
                      "+f"(acc[mt][nt][2]), "+f"(acc[mt][nt][3])
                    : "r"(a[mt][0]), "r"(a[mt][1]), "r"(a[mt][2]), "r"(a[mt][3]),
                      "r"(bfr[nt][0]), "r"(bfr[nt][1]));
            }
    }

    // ---- epilogue: d = sqrt(max(sqi + sqj - 2*dot, 0) + eps) ----
    const float* sqi_s = (const float*)(smem + SM_SQI);
    const float* sqj_s = (const float*)(smem + SM_SQJ);
    float2 sqj2[4];
#pragma unroll
    for (int nt = 0; nt < 4; nt++)
        sqj2[nt] = *(const float2*)&sqj_s[wn + 8 * nt + 2 * cc];

#pragma unroll
    for (int mt = 0; mt < 4; mt++) {
#pragma unroll
        for (int h = 0; h < 2; h++) {
            int row = wm + 16 * mt + 8 * h + g;
            float si = sqi_s[row];
            float* orow = out + ((size_t)(b * N_ + i0 + row)) * N_ + j0 + wn;
#pragma unroll
            for (int nt = 0; nt < 4; nt++) {
                float d0 = acc[mt][nt][2 * h];
                float d1 = acc[mt][nt][2 * h + 1];
                float v0 = sqrtf(fmaxf(fmaf(-2.f, d0, si + sqj2[nt].x), 0.f) + 1e-7f);
                float v1 = sqrtf(fmaxf(fmaf(-2.f, d1, si + sqj2[nt].y), 0.f) + 1e-7f);
                *(float2*)(orow + 8 * nt + 2 * cc) = make_float2(v0, v1);
            }
        }
    }
}

extern "C" void kernel_launch(void* const* d_in, const int* in_sizes, int n_in,
                              void* d_out, int out_size) {
    const float* x = (const float*)d_in[0];
    float* out = (float*)d_out;

    sq_kernel<<<(B_ * N_) / 256, 256>>>(x);

    cudaFuncSetAttribute(edm_mma_kernel, cudaFuncAttributeMaxDynamicSharedMemorySize, SM_TOTAL);
    dim3 grid(N_ / 128, N_ / 128, B_);
    edm_mma_kernel<<<grid, 256, SM_TOTAL>>>(x, out);
}